// round 13
// baseline (speedup 1.0000x reference)
#include <cuda_runtime.h>
#include <cuda_fp16.h>
#include <cstdint>

#define N_DIM 16384
#define D_DIM 10240
#define C_DIM 128
#define NUM_CHUNK 160           // chunks of 64 k
#define THREADS 256
#define BSTRIDE 160             // smem bytes per class row (128 data + 32 pad)

// Device-resolved input bindings (selector kernel writes these).
__device__ const float* g_x;
__device__ const float* g_am;

__global__ void select_inputs_kernel(const float* a, const float* b) {
    bool a_is_am = true;
    for (int i = 0; i < 64; ++i) {
        float v = a[i];
        if (v != 1.0f && v != -1.0f) { a_is_am = false; break; }
    }
    g_x  = a_is_am ? b : a;
    g_am = a_is_am ? a : b;
}

static __device__ __forceinline__ uint32_t smem_u32(const void* p) {
    uint32_t a;
    asm("{ .reg .u64 t; cvta.to.shared.u64 t, %1; cvt.u32.u64 %0, t; }" : "=r"(a) : "l"(p));
    return a;
}
static __device__ __forceinline__ uint32_t f16x2_rn(float2 v) {
    __half2 h2 = __float22half2_rn(v);
    return reinterpret_cast<uint32_t&>(h2);
}
// 2-way exact split of a float2 into f16x2 hi/mid; residual <= 2^-23 |x|
static __device__ __forceinline__ void split2(float2 v, uint32_t& h, uint32_t& m) {
    __half2 h2 = __float22half2_rn(v);
    float2 hf = __half22float2(h2);
    __half2 m2 = __float22half2_rn(make_float2(v.x - hf.x, v.y - hf.y));
    h = reinterpret_cast<uint32_t&>(h2);
    m = reinterpret_cast<uint32_t&>(m2);
}

#define MMA16816(d, a0_, a1_, a2_, a3_, b0_, b1_)                                 \
    asm volatile("mma.sync.aligned.m16n8k16.row.col.f32.f16.f16.f32 "             \
                 "{%0,%1,%2,%3}, {%4,%5,%6,%7}, {%8,%9}, {%0,%1,%2,%3};"          \
                 : "+f"((d)[0]), "+f"((d)[1]), "+f"((d)[2]), "+f"((d)[3])         \
                 : "r"(a0_), "r"(a1_), "r"(a2_), "r"(a3_), "r"(b0_), "r"(b1_))

__global__ void __launch_bounds__(THREADS, 2)
hd_mma_kernel(float* __restrict__ out) {
    // B tile for one 64-k chunk: class c, kstep ks (0..3), slot s (0..3).
    // slot s holds fp16 elements {k=ks*16+2s, +1, ks*16+2s+8, +9} as 8 bytes.
    __shared__ __align__(16) char smb[C_DIM * BSTRIDE];
    __shared__ float rbest[64];
    __shared__ int   rbi[64];
    const uint32_t sb = smem_u32(smb);

    const float* __restrict__ x  = g_x;
    const float* __restrict__ am = g_am;

    const int tid = threadIdx.x;
    const int w = tid >> 5, l = tid & 31;
    const int mg = w >> 1;        // m-group: rows mg*16 .. +15 (of CTA's 64)
    const int h2 = w & 1;         // class half: classes h2*64 .. +63
    const int lg = l >> 2;        // lane group = row within m16 tile (PTX A frag)
    const int lt = l & 3;         // thread in group (PTX A frag)

    // ---- A: direct-gmem fragment pointers (PTX m16n8k16 A layout) ----
    const float* pr0 = x + ((size_t)blockIdx.x * 64 + mg * 16 + lg) * D_DIM + lt * 2;
    const float* pr8 = pr0 + (size_t)8 * D_DIM;

    // ---- B producer mapping: thread covers classes c0+16i (i=0..7) ----
    const int c0 = tid >> 4;
    const int ks0 = (tid >> 2) & 3;
    const int s0 = tid & 3;
    const float* bsrc0 = am + (size_t)c0 * D_DIM + ks0 * 16 + s0 * 2;
    const uint32_t bdst0 = sb + (uint32_t)(c0 * BSTRIDE + ks0 * 32 + s0 * 8);

    float acc[8][4];
#pragma unroll
    for (int n = 0; n < 8; ++n)
#pragma unroll
        for (int e = 0; e < 4; ++e) acc[n][e] = 0.0f;

    // B prefetch, packed to fp16 at load time (am is +/-1: exact). 16 regs.
    uint32_t bP[8][2];
#pragma unroll
    for (int i = 0; i < 8; ++i) {
        const float* s = bsrc0 + (size_t)i * 16 * D_DIM;
        bP[i][0] = f16x2_rn(*(const float2*)(s));
        bP[i][1] = f16x2_rn(*(const float2*)(s + 8));
    }

    // A register prefetch: full chunk (4 ksteps x 4 fragments), refilled in place.
    float2 va[4][4];
#pragma unroll
    for (int j = 0; j < 4; ++j) {
        const int off = j * 16;
        va[j][0] = *(const float2*)(pr0 + off);
        va[j][1] = *(const float2*)(pr8 + off);
        va[j][2] = *(const float2*)(pr0 + off + 8);
        va[j][3] = *(const float2*)(pr8 + off + 8);
    }

    for (int ch = 0; ch < NUM_CHUNK; ++ch) {
        __syncthreads();   // prior chunk's LDS reads complete
#pragma unroll
        for (int i = 0; i < 8; ++i)
            asm volatile("st.shared.v2.b32 [%0], {%1, %2};"
                         :: "r"(bdst0 + (uint32_t)(i * 16 * BSTRIDE)),
                            "r"(bP[i][0]), "r"(bP[i][1]) : "memory");
        __syncthreads();

        const bool more = (ch + 1 < NUM_CHUNK);
        if (more) {
#pragma unroll
            for (int i = 0; i < 8; ++i) {
                const float* s = bsrc0 + (size_t)i * 16 * D_DIM + (ch + 1) * 64;
                bP[i][0] = f16x2_rn(*(const float2*)(s));
                bP[i][1] = f16x2_rn(*(const float2*)(s + 8));
            }
        }

#pragma unroll
        for (int j = 0; j < 4; ++j) {
            // Split current A fragments
            uint32_t ah[4], amd[4];
            split2(va[j][0], ah[0], amd[0]);
            split2(va[j][1], ah[1], amd[1]);
            split2(va[j][2], ah[2], amd[2]);
            split2(va[j][3], ah[3], amd[3]);

            // Refill va[j] from next chunk (load->use distance = 4 ksteps)
            if (more) {
                const int off = (ch + 1) * 64 + j * 16;
                va[j][0] = *(const float2*)(pr0 + off);
                va[j][1] = *(const float2*)(pr8 + off);
                va[j][2] = *(const float2*)(pr0 + off + 8);
                va[j][3] = *(const float2*)(pr8 + off + 8);
            }

            // Load this warp's 8 B fragment pairs (class half h2)
            uint32_t breg[16];
            const uint32_t bbase = sb + (uint32_t)(h2 * 64 * BSTRIDE + j * 32 + lt * 8);
#pragma unroll
            for (int n = 0; n < 8; ++n) {
                const int c = n * 8 + lg;
                asm volatile("ld.shared.v2.b32 {%0, %1}, [%2];"
                             : "=r"(breg[2 * n]), "=r"(breg[2 * n + 1])
                             : "r"(bbase + (uint32_t)(c * BSTRIDE)));
            }

            // split-outer / n-inner: 8 distinct accumulators between reuses
#pragma unroll
            for (int n = 0; n < 8; ++n)
                MMA16816(acc[n], ah[0], ah[1], ah[2], ah[3], breg[2 * n], breg[2 * n + 1]);
#pragma unroll
            for (int n = 0; n < 8; ++n)
                MMA16816(acc[n], amd[0], amd[1], amd[2], amd[3], breg[2 * n], breg[2 * n + 1]);
        }
    }

    // ---- epilogue ----
    // acc[n][e]: row(CTA) = mg*16 + (e<2 ? lg : lg+8), class = h2*64 + n*8 + lt*2 + (e&1)
    float pb[2]; int pi[2];
#pragma unroll
    for (int h = 0; h < 2; ++h) {
        float best = -3.402823466e38f;
        int bi = 0;
#pragma unroll
        for (int n = 0; n < 8; ++n)
#pragma unroll
            for (int e = 0; e < 2; ++e) {
                float v = acc[n][h * 2 + e];
                int c = h2 * 64 + n * 8 + lt * 2 + e;
                if (v > best) { best = v; bi = c; }
            }
#pragma unroll
        for (int ofs = 1; ofs < 4; ofs <<= 1) {
            float ov = __shfl_xor_sync(0xffffffffu, best, ofs);
            int oi = __shfl_xor_sync(0xffffffffu, bi, ofs);
            if (ov > best || (ov == best && oi < bi)) { best = ov; bi = oi; }
        }
        pb[h] = best; pi[h] = bi;
    }

    __syncthreads();   // B-tile LDS done; also orders rbest/rbi reuse
    if (h2 == 1 && lt == 0) {
#pragma unroll
        for (int h = 0; h < 2; ++h) {
            rbest[mg * 16 + h * 8 + lg] = pb[h];
            rbi[mg * 16 + h * 8 + lg] = pi[h];
        }
    }
    __syncthreads();
    if (h2 == 0 && lt == 0) {
#pragma unroll
        for (int h = 0; h < 2; ++h) {
            int r = mg * 16 + h * 8 + lg;
            float ov = rbest[r]; int oi = rbi[r];
            float best = pb[h]; int bi = pi[h];
            if (ov > best || (ov == best && oi < bi)) { best = ov; bi = oi; }
            out[blockIdx.x * 64 + r] = (float)bi;   // float32 output
        }
    }
}

extern "C" void kernel_launch(void* const* d_in, const int* in_sizes, int n_in,
                              void* d_out, int out_size) {
    const float* a = (const float*)d_in[0];
    const float* b = (const float*)d_in[1];

    select_inputs_kernel<<<1, 1>>>(a, b);
    hd_mma_kernel<<<N_DIM / 64, THREADS>>>((float*)d_out);
}

// round 14
// speedup vs baseline: 2.0210x; 2.0210x over previous
#include <cuda_runtime.h>
#include <cuda_fp16.h>
#include <cstdint>

#define N_DIM 16384
#define D_DIM 10240
#define C_DIM 128
#define NUM_CHUNK 160           // chunks of 64 k
#define THREADS 256
#define BSTRIDE 160             // smem bytes per class row (128 data + 32 pad)
#define STAGE_BYTES (C_DIM * BSTRIDE)      // 20480
#define STAGES 4
#define SMEM_BYTES (STAGES * STAGE_BYTES)  // 81920

// Device-resolved input bindings (selector kernel writes these).
__device__ const float* g_x;
__device__ const float* g_am;

// am pre-packed to fp16 fragment-slot layout, 128 B per (chunk, class):
// [ch][c][ks(4)][s(4)] -> 8 B = f16x2{k,k+1}, f16x2{k+8,k+9}, k = ch*64+ks*16+s*2
__device__ __align__(16) uint2 g_bm[(size_t)NUM_CHUNK * C_DIM * 16];

__global__ void select_inputs_kernel(const float* a, const float* b) {
    bool a_is_am = true;
    for (int i = 0; i < 64; ++i) {
        float v = a[i];
        if (v != 1.0f && v != -1.0f) { a_is_am = false; break; }
    }
    g_x  = a_is_am ? b : a;
    g_am = a_is_am ? a : b;
}

static __device__ __forceinline__ uint32_t smem_u32(const void* p) {
    uint32_t a;
    asm("{ .reg .u64 t; cvta.to.shared.u64 t, %1; cvt.u32.u64 %0, t; }" : "=r"(a) : "l"(p));
    return a;
}
static __device__ __forceinline__ uint32_t f16x2_rn(float2 v) {
    __half2 h2 = __float22half2_rn(v);
    return reinterpret_cast<uint32_t&>(h2);
}
// 2-way exact split of a float2 into f16x2 hi/mid; residual <= 2^-24 |x|
static __device__ __forceinline__ void split2(float2 v, uint32_t& h, uint32_t& m) {
    __half2 h2 = __float22half2_rn(v);
    float2 hf = __half22float2(h2);
    __half2 m2 = __float22half2_rn(make_float2(v.x - hf.x, v.y - hf.y));
    h = reinterpret_cast<uint32_t&>(h2);
    m = reinterpret_cast<uint32_t&>(m2);
}

// Pack kernel: one thread per 8-byte slot. 160*128*16 slots.
__global__ void am_pack_kernel() {
    const float* am = g_am;
    int idx = blockIdx.x * blockDim.x + threadIdx.x;
    int ch = idx >> 11;            // /(128*16)
    int r  = idx & 2047;
    int c  = r >> 4;
    int q  = r & 15;               // ks*4 + s
    int ks = q >> 2, s = q & 3;
    const float* p = am + (size_t)c * D_DIM + ch * 64 + ks * 16 + s * 2;
    g_bm[idx] = make_uint2(f16x2_rn(*(const float2*)p),
                           f16x2_rn(*(const float2*)(p + 8)));
}

// fp32-accum MMA (hi split)
#define MMA_F32(d, a0_, a1_, a2_, a3_, b0_, b1_)                                  \
    asm volatile("mma.sync.aligned.m16n8k16.row.col.f32.f16.f16.f32 "             \
                 "{%0,%1,%2,%3}, {%4,%5,%6,%7}, {%8,%9}, {%0,%1,%2,%3};"          \
                 : "+f"((d)[0]), "+f"((d)[1]), "+f"((d)[2]), "+f"((d)[3])         \
                 : "r"(a0_), "r"(a1_), "r"(a2_), "r"(a3_), "r"(b0_), "r"(b1_))

// fp16-accum MMA (mid split; values ~1e-1, error ~2e-3 total)
#define MMA_F16(d, a0_, a1_, a2_, a3_, b0_, b1_)                                  \
    asm volatile("mma.sync.aligned.m16n8k16.row.col.f16.f16.f16.f16 "             \
                 "{%0,%1}, {%2,%3,%4,%5}, {%6,%7}, {%0,%1};"                      \
                 : "+r"((d)[0]), "+r"((d)[1])                                     \
                 : "r"(a0_), "r"(a1_), "r"(a2_), "r"(a3_), "r"(b0_), "r"(b1_))

__global__ void __launch_bounds__(THREADS, 1)
hd_mma_kernel(float* __restrict__ out) {
    extern __shared__ __align__(16) char smb[];
    const uint32_t sb = smem_u32(smb);

    const float* __restrict__ x = g_x;

    const int tid = threadIdx.x;
    const int w = tid >> 5, l = tid & 31;
    const int lg = l >> 2;        // lane group = row within m16 tile (PTX A frag)
    const int lt = l & 3;         // thread in group (PTX A frag)

    // ---- A: direct-gmem fragment pointers (PTX m16n8k16 A layout) ----
    const float* pr0 = x + ((size_t)blockIdx.x * 128 + w * 16 + lg) * D_DIM + lt * 2;
    const float* pr8 = pr0 + (size_t)8 * D_DIM;

    // ---- cp.async producer mapping: unit u = tid + i*256 -> class u>>3, 16B-off u&7
    const int pc = tid >> 3;
    const int po = tid & 7;
    const uint32_t pdst = (uint32_t)(pc * BSTRIDE + po * 16);
    const char* psrc0 = (const char*)g_bm + pc * 128 + po * 16;

    float acc[16][4];
    uint32_t accm[16][2];
#pragma unroll
    for (int n = 0; n < 16; ++n) {
#pragma unroll
        for (int e = 0; e < 4; ++e) acc[n][e] = 0.0f;
        accm[n][0] = 0u; accm[n][1] = 0u;
    }

    auto issue_b = [&](int ci) {
        uint32_t dst = sb + (uint32_t)(ci & (STAGES - 1)) * STAGE_BYTES + pdst;
        const char* src = psrc0 + (size_t)ci * (C_DIM * 128);
#pragma unroll
        for (int i = 0; i < 4; ++i)
            asm volatile("cp.async.cg.shared.global [%0], [%1], 16;"
                         :: "r"(dst + (uint32_t)(i * 32 * BSTRIDE)),
                            "l"(src + (size_t)i * 32 * 128) : "memory");
        asm volatile("cp.async.commit_group;" ::: "memory");
    };

    issue_b(0); issue_b(1); issue_b(2);

    // A register prefetch: full chunk (4 ksteps x 4 fragments), refilled in place.
    float2 va[4][4];
#pragma unroll
    for (int j = 0; j < 4; ++j) {
        const int off = j * 16;
        va[j][0] = *(const float2*)(pr0 + off);
        va[j][1] = *(const float2*)(pr8 + off);
        va[j][2] = *(const float2*)(pr0 + off + 8);
        va[j][3] = *(const float2*)(pr8 + off + 8);
    }

    for (int ch = 0; ch < NUM_CHUNK; ++ch) {
        asm volatile("cp.async.wait_group 2;" ::: "memory");
        __syncthreads();
        if (ch + 3 < NUM_CHUNK) issue_b(ch + 3);
        else asm volatile("cp.async.commit_group;" ::: "memory");  // keep cadence

        const bool more = (ch + 1 < NUM_CHUNK);
        const uint32_t stage = sb + (uint32_t)(ch & (STAGES - 1)) * STAGE_BYTES;

#pragma unroll
        for (int j = 0; j < 4; ++j) {
            // Split current A fragments
            uint32_t ah[4], amd[4];
            split2(va[j][0], ah[0], amd[0]);
            split2(va[j][1], ah[1], amd[1]);
            split2(va[j][2], ah[2], amd[2]);
            split2(va[j][3], ah[3], amd[3]);

            // Refill va[j] from next chunk (load->use distance = 4 ksteps)
            if (more) {
                const int off = (ch + 1) * 64 + j * 16;
                va[j][0] = *(const float2*)(pr0 + off);
                va[j][1] = *(const float2*)(pr8 + off);
                va[j][2] = *(const float2*)(pr0 + off + 8);
                va[j][3] = *(const float2*)(pr8 + off + 8);
            }

            // Load all 16 B fragment pairs (conflict-free, stride 40 words)
            uint32_t breg[32];
            const uint32_t bbase = stage + (uint32_t)(j * 32 + lt * 8);
#pragma unroll
            for (int n = 0; n < 16; ++n) {
                const int c = n * 8 + lg;
                asm volatile("ld.shared.v2.b32 {%0, %1}, [%2];"
                             : "=r"(breg[2 * n]), "=r"(breg[2 * n + 1])
                             : "r"(bbase + (uint32_t)(c * BSTRIDE)));
            }

            // hi split: fp32 accum; mid split: fp16 accum (2x rate)
#pragma unroll
            for (int n = 0; n < 16; ++n)
                MMA_F32(acc[n], ah[0], ah[1], ah[2], ah[3], breg[2 * n], breg[2 * n + 1]);
#pragma unroll
            for (int n = 0; n < 16; ++n)
                MMA_F16(accm[n], amd[0], amd[1], amd[2], amd[3], breg[2 * n], breg[2 * n + 1]);
        }
    }

    // ---- epilogue: merge hi + mid, per-row first-max argmax ----
    // hi acc[n][e]: row = w*16 + (e<2 ? lg : lg+8), col = n*8 + lt*2 + (e&1)
    // mid accm[n][p]: p=0 -> row lg cols {2lt, 2lt+1} (lo,hi); p=1 -> row lg+8
#pragma unroll
    for (int h = 0; h < 2; ++h) {
        float best = -3.402823466e38f;
        int bi = 0;
#pragma unroll
        for (int n = 0; n < 16; ++n) {
            __half2 mh = reinterpret_cast<__half2&>(accm[n][h]);
            float2 mf = __half22float2(mh);
            float v0 = acc[n][h * 2] + mf.x;
            float v1 = acc[n][h * 2 + 1] + mf.y;
            int c = n * 8 + lt * 2;
            if (v0 > best) { best = v0; bi = c; }
            if (v1 > best) { best = v1; bi = c + 1; }
        }
#pragma unroll
        for (int ofs = 1; ofs < 4; ofs <<= 1) {
            float ov = __shfl_xor_sync(0xffffffffu, best, ofs);
            int oi = __shfl_xor_sync(0xffffffffu, bi, ofs);
            if (ov > best || (ov == best && oi < bi)) { best = ov; bi = oi; }
        }
        if (lt == 0)
            out[blockIdx.x * 128 + w * 16 + h * 8 + lg] = (float)bi;  // float32 output
    }
}

extern "C" void kernel_launch(void* const* d_in, const int* in_sizes, int n_in,
                              void* d_out, int out_size) {
    const float* a = (const float*)d_in[0];
    const float* b = (const float*)d_in[1];

    select_inputs_kernel<<<1, 1>>>(a, b);
    am_pack_kernel<<<(NUM_CHUNK * C_DIM * 16) / 256, 256>>>();

    cudaFuncSetAttribute(hd_mma_kernel,
                         cudaFuncAttributeMaxDynamicSharedMemorySize, SMEM_BYTES);
    hd_mma_kernel<<<N_DIM / 128, THREADS, SMEM_BYTES>>>((float*)d_out);
}